// round 17
// baseline (speedup 1.0000x reference)
#include <cuda_runtime.h>
#include <math.h>

#define BB 4096
#define NN 64

// Per-CTA smem (floats), 108,544 bytes -> 2 CTAs/SM:
//  sh_z [64][20]  = 1280
//  sh_c [64][132] = 8448
//  sq   [64][68]  = 4352  q -> clat (C2) -> h staging lo / sred (D)
//  sk   [64][68]  = 4352  k -> h staging hi / sred (D)
//  sv   [64][68]  = 4352  v
//  sat  [64][68]  = 4352  scores/attn -> gate/cand (D/E)
#define OFF_Z   0
#define OFF_C   1280
#define OFF_Q   9728
#define OFF_K   14080
#define OFF_V   18432
#define OFF_AT  22784
#define SMEM_FLOATS 27136

typedef unsigned long long ull;

__device__ __forceinline__ ull pk(float a, float b) {
    ull r; asm("mov.b64 %0, {%1, %2};" : "=l"(r) : "f"(a), "f"(b)); return r;
}
__device__ __forceinline__ void upk(ull v, float& a, float& b) {
    asm("mov.b64 {%0, %1}, %2;" : "=f"(a), "=f"(b) : "l"(v));
}
#define FMAX2(acc, a, b) asm("fma.rn.f32x2 %0, %1, %2, %0;" : "+l"(acc) : "l"(a), "l"(b))

__device__ __forceinline__ float wsum32(float v) {
    #pragma unroll
    for (int m = 16; m > 0; m >>= 1) v += __shfl_xor_sync(0xffffffffu, v, m);
    return v;
}

// Phase-D inner: 4 tokens (delta-8 rows, smem x) x 16 outputs over n4*4 k-rows; w via LDG.
__device__ __forceinline__ void d_accum(const float* __restrict__ x0, int xs,
                                        const float* __restrict__ wsel, int ibase,
                                        int n4, int j4, ull acc[4][2]) {
    for (int s = 0; s < n4; s++) {
        const int il = s << 2;
        float4 x4[4];
        #pragma unroll
        for (int c = 0; c < 4; c++)
            x4[c] = *reinterpret_cast<const float4*>(x0 + c * 8 * xs + il);
        const float4* wr = reinterpret_cast<const float4*>(wsel + (ibase + il) * 16) + j4;
        #pragma unroll
        for (int r = 0; r < 4; r++) {
            float4 w4 = __ldg(wr + r * 4);
            ull wlo = pk(w4.x, w4.y), whi = pk(w4.z, w4.w);
            #pragma unroll
            for (int c = 0; c < 4; c++) {
                float xv = (r == 0) ? x4[c].x : (r == 1) ? x4[c].y : (r == 2) ? x4[c].z : x4[c].w;
                ull xd = pk(xv, xv);
                FMAX2(acc[c][0], xd, wlo);
                FMAX2(acc[c][1], xd, whi);
            }
        }
    }
}

__global__ __launch_bounds__(512, 2)
void memetic_fused_kernel(
    const float* __restrict__ h, const float* __restrict__ u, const float* __restrict__ z,
    const float* __restrict__ qd_down, const float* __restrict__ qd_up,
    const float* __restrict__ kd_down, const float* __restrict__ kd_up,
    const float* __restrict__ vd_down, const float* __restrict__ vd_up,
    const float* __restrict__ od_down, const float* __restrict__ od_up,
    const float* __restrict__ ug_w, const float* __restrict__ ug_b,
    const float* __restrict__ cand_w, const float* __restrict__ cand_b,
    const float* __restrict__ eta_logit,
    float* __restrict__ out_c, float* __restrict__ out_z,
    float* __restrict__ out_attn, float* __restrict__ out_q,
    float* __restrict__ out_k, float* __restrict__ out_v)
{
    extern __shared__ float sm[];
    float* sh_z = sm + OFF_Z;
    float* sh_c = sm + OFF_C;
    float* sq   = sm + OFF_Q;
    float* sk   = sm + OFF_K;
    float* sv   = sm + OFF_V;
    float* sat  = sm + OFF_AT;
    float* sclat = sq;           // alias: q dead after C1
    float* hst   = sq;           // alias: sq+sk contiguous, h staging [64][132] in D
    float* sred  = sq;           // alias: reduction scratch after staging done
    float* sgc   = sat;          // alias: at dead after C2

    const int b    = blockIdx.x;
    const int tid  = threadIdx.x;
    const int wid  = tid >> 5;
    const int lane = tid & 31;
    const float NEG_INF = __int_as_float(0xff800000);
    const float* hb = h + (size_t)b * (NN * 256);
    const float4* hb4 = reinterpret_cast<const float4*>(hb);

    // ---------------- Phase A: stage z ----------------
    {
        const float* zb = z + (size_t)b * (NN * 16);
        for (int i = tid; i < NN * 16; i += 512)
            sh_z[(i >> 4) * 20 + (i & 15)] = zb[i];
    }
    __syncthreads();

    // ---------------- Phase B (warp-specialized): q warps 0-7, k warps 8-11, v warps 12-15 ----
    if (wid < 8) {
        const float4* qdd4 = reinterpret_cast<const float4*>(qd_down);
        // per-lane weight rows for vectorized h loads: qw[it2*4+j] = qd_down row 4*(lane+32*it2)+j
        float4 qw[8];
        #pragma unroll
        for (int it2 = 0; it2 < 2; it2++)
            #pragma unroll
            for (int j = 0; j < 4; j++)
                qw[it2 * 4 + j] = __ldg(qdd4 + 4 * (lane + 32 * it2) + j);
        float4 qwz = make_float4(0.f, 0.f, 0.f, 0.f);
        if (lane < 16) qwz = __ldg(qdd4 + 256 + lane);
        float2 qu2[4];
        #pragma unroll
        for (int r = 0; r < 4; r++)
            qu2[r] = __ldg(reinterpret_cast<const float2*>(qd_up + r * 64) + lane);
        for (int c0 = 0; c0 < 8; c0++) {
            const int t = (wid << 3) + c0;
            const float4* hrow4 = hb4 + t * 64;
            float xz = (lane < 16) ? sh_z[t * 20 + lane] : 0.f;
            float q0 = xz * qwz.x, q1 = xz * qwz.y, q2 = xz * qwz.z, q3 = xz * qwz.w;
            #pragma unroll
            for (int it2 = 0; it2 < 2; it2++) {
                float4 x = __ldg(hrow4 + lane + 32 * it2);
                const float4* w = qw + it2 * 4;
                q0 += x.x * w[0].x + x.y * w[1].x + x.z * w[2].x + x.w * w[3].x;
                q1 += x.x * w[0].y + x.y * w[1].y + x.z * w[2].y + x.w * w[3].y;
                q2 += x.x * w[0].z + x.y * w[1].z + x.z * w[2].z + x.w * w[3].z;
                q3 += x.x * w[0].w + x.y * w[1].w + x.z * w[2].w + x.w * w[3].w;
            }
            q0 = wsum32(q0); q1 = wsum32(q1); q2 = wsum32(q2); q3 = wsum32(q3);
            const size_t tok = (size_t)(b * NN + t);
            float2 qv;
            qv.x = 0.25f * (q0 * qu2[0].x + q1 * qu2[1].x + q2 * qu2[2].x + q3 * qu2[3].x);
            qv.y = 0.25f * (q0 * qu2[0].y + q1 * qu2[1].y + q2 * qu2[2].y + q3 * qu2[3].y);
            *reinterpret_cast<float2*>(sq + t * 68 + 2 * lane) = qv;
            *reinterpret_cast<float2*>(out_q + tok * 64 + 2 * lane) = qv;
        }
    } else if (wid < 12) {
        const float4* ub4 = reinterpret_cast<const float4*>(u + (size_t)b * (NN * 128));
        const float4* kdd4 = reinterpret_cast<const float4*>(kd_down);
        float4 kw[4];
        #pragma unroll
        for (int j = 0; j < 4; j++) kw[j] = __ldg(kdd4 + 4 * lane + j);
        float2 ku2[4];
        #pragma unroll
        for (int r = 0; r < 4; r++)
            ku2[r] = __ldg(reinterpret_cast<const float2*>(kd_up + r * 64) + lane);
        const int w2 = wid - 8;
        for (int c0 = 0; c0 < 16; c0++) {
            const int t = (w2 << 4) + c0;
            float4 x = __ldg(ub4 + t * 32 + lane);
            float k0 = x.x * kw[0].x + x.y * kw[1].x + x.z * kw[2].x + x.w * kw[3].x;
            float k1 = x.x * kw[0].y + x.y * kw[1].y + x.z * kw[2].y + x.w * kw[3].y;
            float k2 = x.x * kw[0].z + x.y * kw[1].z + x.z * kw[2].z + x.w * kw[3].z;
            float k3 = x.x * kw[0].w + x.y * kw[1].w + x.z * kw[2].w + x.w * kw[3].w;
            k0 = wsum32(k0); k1 = wsum32(k1); k2 = wsum32(k2); k3 = wsum32(k3);
            const size_t tok = (size_t)(b * NN + t);
            float2 kv;
            kv.x = 0.25f * (k0 * ku2[0].x + k1 * ku2[1].x + k2 * ku2[2].x + k3 * ku2[3].x);
            kv.y = 0.25f * (k0 * ku2[0].y + k1 * ku2[1].y + k2 * ku2[2].y + k3 * ku2[3].y);
            *reinterpret_cast<float2*>(sk + t * 68 + 2 * lane) = kv;
            *reinterpret_cast<float2*>(out_k + tok * 64 + 2 * lane) = kv;
        }
    } else {
        const float4* ub4 = reinterpret_cast<const float4*>(u + (size_t)b * (NN * 128));
        const float4* vdd4 = reinterpret_cast<const float4*>(vd_down);
        float4 vw[4];
        #pragma unroll
        for (int j = 0; j < 4; j++) vw[j] = __ldg(vdd4 + 4 * lane + j);
        float2 vu2[4];
        #pragma unroll
        for (int r = 0; r < 4; r++)
            vu2[r] = __ldg(reinterpret_cast<const float2*>(vd_up + r * 64) + lane);
        const int w2 = wid - 12;
        for (int c0 = 0; c0 < 16; c0++) {
            const int t = (w2 << 4) + c0;
            float4 x = __ldg(ub4 + t * 32 + lane);
            float v0 = x.x * vw[0].x + x.y * vw[1].x + x.z * vw[2].x + x.w * vw[3].x;
            float v1 = x.x * vw[0].y + x.y * vw[1].y + x.z * vw[2].y + x.w * vw[3].y;
            float v2 = x.x * vw[0].z + x.y * vw[1].z + x.z * vw[2].z + x.w * vw[3].z;
            float v3 = x.x * vw[0].w + x.y * vw[1].w + x.z * vw[2].w + x.w * vw[3].w;
            v0 = wsum32(v0); v1 = wsum32(v1); v2 = wsum32(v2); v3 = wsum32(v3);
            const size_t tok = (size_t)(b * NN + t);
            float2 vv;
            vv.x = 0.25f * (v0 * vu2[0].x + v1 * vu2[1].x + v2 * vu2[2].x + v3 * vu2[3].x);
            vv.y = 0.25f * (v0 * vu2[0].y + v1 * vu2[1].y + v2 * vu2[2].y + v3 * vu2[3].y);
            *reinterpret_cast<float2*>(sv + t * 68 + 2 * lane) = vv;
            *reinterpret_cast<float2*>(out_v + tok * 64 + 2 * lane) = vv;
        }
    }
    __syncthreads();

    // ---------------- Phase C1: QK scores; 16n x 32m tiles, thread 4x4, 2-warp d-split ----------------
    {
        const int tile = wid >> 1, ks = wid & 1;
        const int nb = ((tile >> 1) << 4) + (lane & 3);
        const int mb = ((tile & 1) << 5) + (lane >> 2);
        ull acc[4][4];
        #pragma unroll
        for (int a = 0; a < 4; a++)
            #pragma unroll
            for (int bb = 0; bb < 4; bb++) acc[a][bb] = 0ull;
        #pragma unroll
        for (int s = 0; s < 8; s++) {
            const int dd = (ks << 5) + (s << 2);
            ull klo[4], khi[4];
            #pragma unroll
            for (int bb = 0; bb < 4; bb++) {
                ulonglong2 kp = *reinterpret_cast<const ulonglong2*>(sk + (mb + 8 * bb) * 68 + dd);
                klo[bb] = kp.x; khi[bb] = kp.y;
            }
            #pragma unroll
            for (int a = 0; a < 4; a++) {
                ulonglong2 qp = *reinterpret_cast<const ulonglong2*>(sq + (nb + 4 * a) * 68 + dd);
                #pragma unroll
                for (int bb = 0; bb < 4; bb++) {
                    FMAX2(acc[a][bb], qp.x, klo[bb]);
                    FMAX2(acc[a][bb], qp.y, khi[bb]);
                }
            }
        }
        float sc[4][4];
        #pragma unroll
        for (int a = 0; a < 4; a++)
            #pragma unroll
            for (int bb = 0; bb < 4; bb++) {
                float lo, hi; upk(acc[a][bb], lo, hi); sc[a][bb] = lo + hi;
            }
        if (ks == 1) {
            #pragma unroll
            for (int a = 0; a < 4; a++)
                #pragma unroll
                for (int bb = 0; bb < 4; bb++)
                    sat[(nb + 4 * a) * 68 + mb + 8 * bb] = sc[a][bb];
        }
        __syncthreads();
        if (ks == 0) {
            #pragma unroll
            for (int a = 0; a < 4; a++) {
                const int n = nb + 4 * a;
                #pragma unroll
                for (int bb = 0; bb < 4; bb++) {
                    const int m = mb + 8 * bb;
                    float r = (sc[a][bb] + sat[n * 68 + m]) * 0.125f;
                    if (n == m) r = NEG_INF;
                    sat[n * 68 + m] = r;
                }
            }
        }
        __syncthreads();
    }

    // ---------------- Phase C1b: softmax, no max pass (scores tiny; exp(-inf)=0 masks) ----------
    {
        #pragma unroll
        for (int rr = 0; rr < 4; rr++) {
            int n = (wid << 2) + rr;
            float2 s01 = *reinterpret_cast<const float2*>(sat + n * 68 + 2 * lane);
            float e0 = __expf(s01.x), e1 = __expf(s01.y);
            float inv = 1.f / wsum32(e0 + e1);
            float2 a01 = make_float2(e0 * inv, e1 * inv);
            *reinterpret_cast<float2*>(sat + n * 68 + 2 * lane) = a01;
            size_t tk = (size_t)(b * NN + n) * 64;
            *reinterpret_cast<float2*>(out_attn + tk + 2 * lane) = a01;
        }
    }
    __syncthreads();

    // ---------------- Phase C2: clat = attn @ v; same tiling, 2-warp m-split ----------------
    {
        const int tile = wid >> 1, ks = wid & 1;
        const int nb = ((tile >> 1) << 4) + (lane & 3);
        const int d0 = ((tile & 1) << 5) + ((lane >> 2) << 2);
        ull acc[4][2];
        #pragma unroll
        for (int a = 0; a < 4; a++) { acc[a][0] = 0ull; acc[a][1] = 0ull; }
        #pragma unroll
        for (int s = 0; s < 8; s++) {
            const int mm = (ks << 5) + (s << 2);
            ull vlo[4], vhi[4];
            #pragma unroll
            for (int t = 0; t < 4; t++) {
                ulonglong2 vp = *reinterpret_cast<const ulonglong2*>(sv + (mm + t) * 68 + d0);
                vlo[t] = vp.x; vhi[t] = vp.y;
            }
            #pragma unroll
            for (int a = 0; a < 4; a++) {
                float4 a4 = *reinterpret_cast<const float4*>(sat + (nb + 4 * a) * 68 + mm);
                ull a0 = pk(a4.x, a4.x), a1 = pk(a4.y, a4.y);
                ull a2 = pk(a4.z, a4.z), a3 = pk(a4.w, a4.w);
                FMAX2(acc[a][0], a0, vlo[0]); FMAX2(acc[a][1], a0, vhi[0]);
                FMAX2(acc[a][0], a1, vlo[1]); FMAX2(acc[a][1], a1, vhi[1]);
                FMAX2(acc[a][0], a2, vlo[2]); FMAX2(acc[a][1], a2, vhi[2]);
                FMAX2(acc[a][0], a3, vlo[3]); FMAX2(acc[a][1], a3, vhi[3]);
            }
        }
        if (ks == 1) {
            #pragma unroll
            for (int a = 0; a < 4; a++) {
                float x0, x1, x2, x3;
                upk(acc[a][0], x0, x1); upk(acc[a][1], x2, x3);
                *reinterpret_cast<float4*>(sclat + (nb + 4 * a) * 68 + d0) =
                    make_float4(x0, x1, x2, x3);
            }
        }
        __syncthreads();
        if (ks == 0) {
            #pragma unroll
            for (int a = 0; a < 4; a++) {
                float4 p = *reinterpret_cast<const float4*>(sclat + (nb + 4 * a) * 68 + d0);
                float x0, x1, x2, x3;
                upk(acc[a][0], x0, x1); upk(acc[a][1], x2, x3);
                *reinterpret_cast<float4*>(sclat + (nb + 4 * a) * 68 + d0) =
                    make_float4(x0 + p.x, x1 + p.y, x2 + p.z, x3 + p.w);
            }
        }
        __syncthreads();
    }

    // ---------------- Phase C3: rank-4 output projection (warp per token, float4 epilogue) --------
    {
        const float4* odd4 = reinterpret_cast<const float4*>(od_down);
        float4 o0 = __ldg(odd4 + lane);
        float4 o1 = __ldg(odd4 + lane + 32);
        float4 ou4[4];
        #pragma unroll
        for (int r = 0; r < 4; r++)
            ou4[r] = __ldg(reinterpret_cast<const float4*>(od_up + r * 128) + lane);
        for (int c0 = 0; c0 < 4; c0++) {
            int t = (wid << 2) + c0;
            float ca = sclat[t * 68 + lane];
            float cb = sclat[t * 68 + lane + 32];
            float r0 = wsum32(ca * o0.x + cb * o1.x);
            float r1 = wsum32(ca * o0.y + cb * o1.y);
            float r2 = wsum32(ca * o0.z + cb * o1.z);
            float r3 = wsum32(ca * o0.w + cb * o1.w);
            size_t tk = (size_t)(b * NN + t) * 128;
            float4 cv;
            cv.x = 0.25f * (r0 * ou4[0].x + r1 * ou4[1].x + r2 * ou4[2].x + r3 * ou4[3].x);
            cv.y = 0.25f * (r0 * ou4[0].y + r1 * ou4[1].y + r2 * ou4[2].y + r3 * ou4[3].y);
            cv.z = 0.25f * (r0 * ou4[0].z + r1 * ou4[1].z + r2 * ou4[2].z + r3 * ou4[3].z);
            cv.w = 0.25f * (r0 * ou4[0].w + r1 * ou4[1].w + r2 * ou4[2].w + r3 * ou4[3].w);
            *reinterpret_cast<float4*>(sh_c + t * 132 + 4 * lane) = cv;
            *reinterpret_cast<float4*>(out_c + tk + 4 * lane) = cv;
        }
    }
    __syncthreads();

    // ---------------- Phase D: gate/cand matmuls; h streamed via 2 big smem chunks ----------------
    {
        const int ip   = wid & 3;
        const int tile = wid >> 2;
        const int th   = tile >> 1;
        const int j0   = (tile & 1) * 16 + (lane >> 3) * 4;   // 0..31
        const int t0   = th * 32 + (lane & 7);                // + 8c -> 4 tokens
        const float* wsel = (j0 < 16) ? ug_w : cand_w;
        const int j4 = (j0 & 15) >> 2;
        ull acc[4][2];
        #pragma unroll
        for (int c = 0; c < 4; c++) { acc[c][0] = 0ull; acc[c][1] = 0ull; }

        // h part: 2 staged chunks of 128 cols through hst (= dead sq+sk, stride 132)
        const int r2 = lane >> 4, c4 = lane & 15;
        #pragma unroll
        for (int ch = 0; ch < 2; ch++) {
            #pragma unroll
            for (int rr = 0; rr < 2; rr++) {
                int row = (wid << 2) + (rr << 1) + r2;
                #pragma unroll
                for (int it = 0; it < 2; it++) {
                    int cc = (it << 4) + c4;
                    float4 v4 = __ldg(hb4 + row * 64 + (ch << 5) + cc);
                    *reinterpret_cast<float4*>(hst + row * 132 + (cc << 2)) = v4;
                }
            }
            __syncthreads();
            d_accum(hst + t0 * 132 + ip * 32, 132, wsel, 16 + (ch << 7) + ip * 32, 8, j4, acc);
            __syncthreads();
        }
        // z part (i 0..15) and c part (i 272..399), split 4 ways by ip
        d_accum(sh_z + t0 * 20 + ip * 4, 20, wsel, ip * 4, 1, j4, acc);
        d_accum(sh_c + t0 * 132 + ip * 32, 132, wsel, 272 + ip * 32, 8, j4, acc);

        float f[4][4];
        #pragma unroll
        for (int c = 0; c < 4; c++) {
            upk(acc[c][0], f[c][0], f[c][1]);
            upk(acc[c][1], f[c][2], f[c][3]);
        }
        // reduction scratch in sred (= sq+sk span, staging done)
        if (ip != 0) {
            float* dst = sred + (tile * 3 + (ip - 1)) * 512;
            #pragma unroll
            for (int c = 0; c < 4; c++)
                #pragma unroll
                for (int d = 0; d < 4; d++)
                    dst[(c * 4 + d) * 32 + lane] = f[c][d];
        }
        __syncthreads();
        if (ip == 0) {
            #pragma unroll
            for (int s = 0; s < 3; s++) {
                const float* src = sred + (tile * 3 + s) * 512;
                #pragma unroll
                for (int c = 0; c < 4; c++)
                    #pragma unroll
                    for (int d = 0; d < 4; d++)
                        f[c][d] += src[(c * 4 + d) * 32 + lane];
            }
            #pragma unroll
            for (int d = 0; d < 4; d++) {
                int j = j0 + d;
                float bias = (j < 16) ? __ldg(ug_b + j) : __ldg(cand_b + j - 16);
                #pragma unroll
                for (int c = 0; c < 4; c++)
                    sgc[(t0 + 8 * c) * 33 + j] = f[c][d] + bias;
            }
        }
    }
    __syncthreads();

    // ---------------- Phase E: gated update + layernorm ----------------
    {
        const float eta = 1.f / (1.f + __expf(-__ldg(eta_logit)));
        const int s = lane >> 4;
        const int j = lane & 15;
        #pragma unroll
        for (int p = 0; p < 2; p++) {
            int t = (wid << 2) + (p << 1) + s;
            float gp = sgc[t * 33 + j];
            float cp = sgc[t * 33 + 16 + j];
            float eg = eta * (1.f / (1.f + __expf(-gp)));
            float val = (1.f - eg) * sh_z[t * 20 + j] + eg * tanhf(cp);
            float sum = val;
            #pragma unroll
            for (int msk = 8; msk > 0; msk >>= 1)
                sum += __shfl_xor_sync(0xffffffffu, sum, msk, 16);
            float mu = sum * (1.f / 16.f);
            float dv = val - mu;
            float vs = dv * dv;
            #pragma unroll
            for (int msk = 8; msk > 0; msk >>= 1)
                vs += __shfl_xor_sync(0xffffffffu, vs, msk, 16);
            float var = vs * (1.f / 16.f);
            out_z[(size_t)(b * NN + t) * 16 + j] = dv * rsqrtf(var + 1e-5f);
        }
    }
}

extern "C" void kernel_launch(void* const* d_in, const int* in_sizes, int n_in,
                              void* d_out, int out_size) {
    const float* h        = (const float*)d_in[0];
    const float* u        = (const float*)d_in[1];
    const float* z        = (const float*)d_in[2];
    const float* qd_down  = (const float*)d_in[3];
    const float* qd_up    = (const float*)d_in[4];
    const float* kd_down  = (const float*)d_in[5];
    const float* kd_up    = (const float*)d_in[6];
    const float* vd_down  = (const float*)d_in[7];
    const float* vd_up    = (const float*)d_in[8];
    const float* od_down  = (const float*)d_in[9];
    const float* od_up    = (const float*)d_in[10];
    const float* ug_w     = (const float*)d_in[11];
    const float* ug_b     = (const float*)d_in[12];
    const float* cand_w   = (const float*)d_in[13];
    const float* cand_b   = (const float*)d_in[14];
    const float* eta_logit= (const float*)d_in[15];

    float* o = (float*)d_out;
    float* out_c    = o;                        // 4096*64*128
    float* out_z    = o + (size_t)33554432;     // 4096*64*16
    float* out_attn = o + (size_t)37748736;     // 4096*64*64
    float* out_q    = o + (size_t)54525952;
    float* out_k    = o + (size_t)71303168;
    float* out_v    = o + (size_t)88080384;

    const int smem_bytes = SMEM_FLOATS * sizeof(float);  // 108544
    cudaFuncSetAttribute(memetic_fused_kernel,
                         cudaFuncAttributeMaxDynamicSharedMemorySize, smem_bytes);

    memetic_fused_kernel<<<BB, 512, smem_bytes>>>(
        h, u, z, qd_down, qd_up, kd_down, kd_up, vd_down, vd_up,
        od_down, od_up, ug_w, ug_b, cand_w, cand_b, eta_logit,
        out_c, out_z, out_attn, out_q, out_k, out_v);
}